// round 8
// baseline (speedup 1.0000x reference)
#include <cuda_runtime.h>
#include <cstdint>
#include <cstddef>

#define BB 1024
#define SS 1024
#define FF 36
#define HH 20
#define FULLMASK 0xffffffffu

typedef unsigned long long ull;

__device__ ull g_h2[(BB / 2) * HH];
__device__ int g_oh64;

// ---------------------------------------------------------------------------
// f32x2 packed helpers
// ---------------------------------------------------------------------------
__device__ __forceinline__ ull pk2(float a, float b) {
    ull r; asm("mov.b64 %0,{%1,%2};" : "=l"(r) : "f"(a), "f"(b)); return r;
}
__device__ __forceinline__ void upk2(ull v, float& a, float& b) {
    asm("mov.b64 {%0,%1},%2;" : "=f"(a), "=f"(b) : "l"(v));
}
__device__ __forceinline__ ull fma2(ull a, ull b, ull c) {
    ull d; asm("fma.rn.f32x2 %0,%1,%2,%3;" : "=l"(d) : "l"(a), "l"(b), "l"(c)); return d;
}
__device__ __forceinline__ ull add2(ull a, ull b) {
    ull d; asm("add.rn.f32x2 %0,%1,%2;" : "=l"(d) : "l"(a), "l"(b)); return d;
}
__device__ __forceinline__ float selh(ull v, int hf) {
    float lo, hi; upk2(v, lo, hi);
    return hf ? hi : lo;
}

__device__ __forceinline__ float tanh_hw(float x) {
    float y; asm("tanh.approx.f32 %0,%1;" : "=f"(y) : "f"(x)); return y;
}

// ---------------------------------------------------------------------------
__global__ void detect_kernel(const int* __restrict__ oh) {
    if (threadIdx.x == 0 && blockIdx.x == 0) {
        int z = 1;
        for (int i = 1; i < 64; i += 2)
            if (oh[i] != 0) { z = 0; break; }
        g_oh64 = z;
    }
}

__global__ void embed_kernel(const float* __restrict__ x,
                             const int* __restrict__ oh,
                             const float* __restrict__ e0,
                             const float* __restrict__ e1,
                             const float* __restrict__ e2,
                             const float* __restrict__ e3,
                             float* __restrict__ origin) {
    int idx = blockIdx.x * blockDim.x + threadIdx.x;
    if (idx >= BB * SS) return;
    int i0, i1, i2, i3;
    if (g_oh64) {
        const int* p = oh + (size_t)idx * 8;
        i0 = p[0]; i1 = p[2]; i2 = p[4]; i3 = p[6];
    } else {
        int4 o = reinterpret_cast<const int4*>(oh)[idx];
        i0 = o.x; i1 = o.y; i2 = o.z; i3 = o.w;
    }
    const float4* xr = reinterpret_cast<const float4*>(x + (size_t)idx * 12);
    float4* out = reinterpret_cast<float4*>(origin + (size_t)idx * FF);
    out[0] = xr[0];
    out[1] = xr[1];
    out[2] = xr[2];
    out[3] = reinterpret_cast<const float4*>(e0)[i0];
    out[4] = reinterpret_cast<const float4*>(e1)[i1];
    const float4* e2p = reinterpret_cast<const float4*>(e2);
    out[5] = e2p[i2 * 2];
    out[6] = e2p[i2 * 2 + 1];
    const float4* e3p = reinterpret_cast<const float4*>(e3);
    out[7] = e3p[i3 * 2];
    out[8] = e3p[i3 * 2 + 1];
}

// ---------------------------------------------------------------------------
// K-split lane-role decomposition: CTA = 128 threads = 1 batch-pair, 4 warps.
// warp w owns units w*5..w*5+4. lane lw = u*6 + g*2 + hf (u<5; lanes 30,31
// idle-duplicate unit 4). Lane computes half (hf) of gate g's dot.
// Roles after xor(1) reduce: g0->r, g1->z (one shared MUFU), g2->n (second
// MUFU after 1 shfl of r). h tracked per-lane (own half) via broadcast shfls.
// ---------------------------------------------------------------------------
struct KCtx {
    ull wx[18], wh[10];
    float b1, b2;
    int base, k, hf;
    bool g2;       // this lane is the n-gate lane
    bool lead;     // u<5 && g==0 && hf==0 -> stores packed h
};

__device__ __forceinline__ void load_kctx(
    KCtx& C, int tid,
    const float* __restrict__ Wih, const float* __restrict__ Whh,
    const float* __restrict__ bih, const float* __restrict__ bhh) {
    int w = tid >> 5, lw = tid & 31;
    int u = lw / 6, rol = lw % 6;
    bool act = (u < 5);
    int uc = act ? u : 4;
    int g = rol >> 1, hf = rol & 1;
    C.k = w * 5 + uc;
    C.base = uc * 6;
    C.hf = hf;
    C.g2 = (g == 2);
    C.lead = act && (rol == 0);
    int row = g * HH + C.k;
#pragma unroll
    for (int f = 0; f < 18; f++) { float v = Wih[row * FF + hf * 18 + f]; C.wx[f] = pk2(v, v); }
#pragma unroll
    for (int j = 0; j < 10; j++) { float v = Whh[row * HH + hf * 10 + j]; C.wh[j] = pk2(v, v); }
    if (C.g2) { C.b1 = bih[2 * HH + C.k]; C.b2 = bhh[2 * HH + C.k]; }
    else      { C.b1 = bih[g * HH + C.k] + bhh[g * HH + C.k]; C.b2 = 0.f; }
}

// One GRU cell step; h_sel is this lane's half of h. Returns raw h_new
// (caller applies tanh for the decoder).
__device__ __forceinline__ float gru_step(
    const KCtx& C, const ull* __restrict__ xc, const ull* __restrict__ hc,
    float h_sel) {
    ull ax0 = 0, ax1 = 0, ah0 = 0, ah1 = 0;
    const ulonglong2* xv = reinterpret_cast<const ulonglong2*>(xc + C.hf * 18);
#pragma unroll
    for (int i = 0; i < 9; i++) {
        ulonglong2 v = xv[i];
        ax0 = fma2(C.wx[2 * i], v.x, ax0);
        ax1 = fma2(C.wx[2 * i + 1], v.y, ax1);
    }
    const ulonglong2* hv = reinterpret_cast<const ulonglong2*>(hc + C.hf * 10);
#pragma unroll
    for (int i = 0; i < 5; i++) {
        ulonglong2 v = hv[i];
        ah0 = fma2(C.wh[2 * i], v.x, ah0);
        ah1 = fma2(C.wh[2 * i + 1], v.y, ah1);
    }
    ull ax = add2(ax0, ax1);
    ull ah = add2(ah0, ah1);
    ull accA = C.g2 ? ax : add2(ax, ah);
    ull accB = ah;
    accA = add2(accA, __shfl_xor_sync(FULLMASK, accA, 1));
    accB = add2(accB, __shfl_xor_sync(FULLMASK, accB, 1));
    float sA = selh(accA, C.hf);
    float sB = selh(accB, C.hf);
    // stage 1: g0 lanes -> r, g1 lanes -> z (single tanh instruction)
    float rz = fmaf(0.5f, tanh_hw(0.5f * (sA + C.b1)), 0.5f);
    float r = __shfl_sync(FULLMASK, rz, C.base + C.hf);
    // stage 2: g2 lanes -> n
    float n = tanh_hw(sA + C.b1 + r * (sB + C.b2));
    float z = __shfl_sync(FULLMASK, rz, C.base + 2 + C.hf);
    float nn = __shfl_sync(FULLMASK, n, C.base + 4 + C.hf);
    return fmaf(z, h_sel - nn, nn);
}

// ---------------------------------------------------------------------------
// Encoder
// ---------------------------------------------------------------------------
__global__ void __launch_bounds__(128, 4) encoder_kernel(
    const float* __restrict__ xin,
    const float* __restrict__ Wih, const float* __restrict__ Whh,
    const float* __restrict__ bih, const float* __restrict__ bhh) {
    __shared__ __align__(16) ull x2s[2][FF];
    __shared__ __align__(16) ull h2s[2][HH];

    int tid = threadIdx.x;
    KCtx C;
    load_kctx(C, tid, Wih, Whh, bih, bhh);

    int gp = blockIdx.x;
    const float* xr0 = xin + (size_t)(gp * 2) * SS * FF;
    const float* xr1 = xin + (size_t)(gp * 2 + 1) * SS * FF;

    float pa = 0.f, pb = 0.f;
    if (tid < FF) {
        x2s[0][tid] = pk2(xr0[tid], xr1[tid]);
        pa = xr0[FF + tid]; pb = xr1[FF + tid];
    }
    if (tid < HH) h2s[0][tid] = 0ULL;
    __syncthreads();

    float h_sel = 0.f;

    auto step = [&](int s, const ull* xc, const ull* hc, ull* xn, ull* hn) {
        if (tid < FF) {
            if (s + 1 < SS) xn[tid] = pk2(pa, pb);
            if (s + 2 < SS) {
                pa = xr0[(size_t)(s + 2) * FF + tid];
                pb = xr1[(size_t)(s + 2) * FF + tid];
            }
        }
        h_sel = gru_step(C, xc, hc, h_sel);
        if (C.lead) {
            float h1 = __shfl_sync(FULLMASK, h_sel, C.base + 1);
            hn[C.k] = pk2(h_sel, h1);
        } else {
            __shfl_sync(FULLMASK, h_sel, C.base + 1);
        }
        __syncthreads();
    };

    for (int s = 0; s < SS; s += 2) {
        step(s, x2s[0], h2s[0], x2s[1], h2s[1]);
        step(s + 1, x2s[1], h2s[1], x2s[0], h2s[0]);
    }

    float t = tanh_hw(h_sel);
    float t1 = __shfl_sync(FULLMASK, t, C.base + 1);
    if (C.lead)
        g_h2[gp * HH + C.k] = pk2(t, t1);
}

// ---------------------------------------------------------------------------
// Decoder: phase 1 = tanh-GRU gates; phase 2 = Wfc projection with lane =
// (feature o, half hf) over 72 lanes, Wfc half-rows in registers.
// ---------------------------------------------------------------------------
__global__ void __launch_bounds__(128, 4) decoder_kernel(
    const float* __restrict__ Wih, const float* __restrict__ Whh,
    const float* __restrict__ bih, const float* __restrict__ bhh,
    const float* __restrict__ Wfc, const float* __restrict__ bfc,
    float* __restrict__ out_xs) {
    __shared__ __align__(16) ull x2s[2][FF];
    __shared__ __align__(16) ull h2s[2][HH];

    int tid = threadIdx.x;
    KCtx C;
    load_kctx(C, tid, Wih, Whh, bih, bhh);

    // Projection role: lanes 0..71: o = feature, pf = K-half & batch-half.
    bool pv = (tid < 72);
    int o = pv ? (tid >> 1) : 35;
    int pf = tid & 1;
    ull wfcp[10];
#pragma unroll
    for (int j = 0; j < 10; j++) { float v = Wfc[o * HH + pf * 10 + j]; wfcp[j] = pk2(v, v); }
    float bo = bfc[o];

    int gp = blockIdx.x;
    float* orow0 = out_xs + (size_t)(gp * 2) * SS * FF;
    float* orow1 = out_xs + (size_t)(gp * 2 + 1) * SS * FF;
    float* orowp = pf ? orow1 : orow0;

    float h_sel = selh(g_h2[gp * HH + C.k], C.hf);
    if (tid < HH) h2s[0][tid] = g_h2[gp * HH + tid];
    __syncthreads();

    auto proj = [&](const ull* hsrc, ull* xdst, int so) {
        ull a0 = 0, a1 = 0;
        const ulonglong2* hv = reinterpret_cast<const ulonglong2*>(hsrc + pf * 10);
#pragma unroll
        for (int i = 0; i < 5; i++) {
            ulonglong2 v = hv[i];
            a0 = fma2(wfcp[2 * i], v.x, a0);
            a1 = fma2(wfcp[2 * i + 1], v.y, a1);
        }
        ull acc = add2(a0, a1);
        acc = add2(acc, __shfl_xor_sync(FULLMASK, acc, 1));
        // lane pf=0 -> batch0 (lo), pf=1 -> batch1 (hi)
        float xv = tanh_hw(selh(acc, pf) + bo);
        float xo = __shfl_xor_sync(FULLMASK, xv, 1);
        if (pv) {
            orowp[(size_t)so * FF + o] = xv;
            if (pf == 0) xdst[o] = pk2(xv, xo);
        }
        __syncthreads();
    };

    proj(h2s[0], x2s[0], SS - 1);

    auto dstep = [&](int st, const ull* xc, const ull* hc, ull* xn, ull* hn) {
        h_sel = tanh_hw(gru_step(C, xc, hc, h_sel));
        float h1 = __shfl_sync(FULLMASK, h_sel, C.base + 1);
        if (C.lead) hn[C.k] = pk2(h_sel, h1);
        __syncthreads();
        proj(hn, xn, SS - 1 - st);
    };

    for (int st = 1; st < SS; st += 2) {
        dstep(st, x2s[0], h2s[0], x2s[1], h2s[1]);
        if (st + 1 < SS)
            dstep(st + 1, x2s[1], h2s[1], x2s[0], h2s[0]);
    }
}

// ---------------------------------------------------------------------------
extern "C" void kernel_launch(void* const* d_in, const int* in_sizes, int n_in,
                              void* d_out, int out_size) {
    const float* x = (const float*)d_in[0];
    const int* oh = (const int*)d_in[1];
    const float* e0 = (const float*)d_in[2];
    const float* e1 = (const float*)d_in[3];
    const float* e2 = (const float*)d_in[4];
    const float* e3 = (const float*)d_in[5];
    const float* Wih1 = (const float*)d_in[6];
    const float* Whh1 = (const float*)d_in[7];
    const float* bih1 = (const float*)d_in[8];
    const float* bhh1 = (const float*)d_in[9];
    const float* Wih2 = (const float*)d_in[10];
    const float* Whh2 = (const float*)d_in[11];
    const float* bih2 = (const float*)d_in[12];
    const float* bhh2 = (const float*)d_in[13];
    const float* Wfc = (const float*)d_in[14];
    const float* bfc = (const float*)d_in[15];

    float* out = (float*)d_out;
    float* origin = out;                          // (B,S,F)
    float* xs = out + (size_t)BB * SS * FF;       // (B,S,F) flipped decode

    detect_kernel<<<1, 32>>>(oh);
    embed_kernel<<<(BB * SS + 255) / 256, 256>>>(x, oh, e0, e1, e2, e3, origin);
    encoder_kernel<<<BB / 2, 128>>>(origin, Wih1, Whh1, bih1, bhh1);
    decoder_kernel<<<BB / 2, 128>>>(Wih2, Whh2, bih2, bhh2, Wfc, bfc, xs);
}

// round 9
// speedup vs baseline: 2.0975x; 2.0975x over previous
#include <cuda_runtime.h>
#include <cstdint>
#include <cstddef>

#define BB 1024
#define SS 1024
#define FF 36
#define HH 20
#define FULLMASK 0xffffffffu

typedef unsigned long long ull;

__device__ float g_h[BB * HH];
__device__ int g_oh64;

// ---------------------------------------------------------------------------
// f32x2 packed helpers (packing = 2 adjacent K-elements of one batch)
// ---------------------------------------------------------------------------
__device__ __forceinline__ ull fma2(ull a, ull b, ull c) {
    ull d; asm("fma.rn.f32x2 %0,%1,%2,%3;" : "=l"(d) : "l"(a), "l"(b), "l"(c)); return d;
}
__device__ __forceinline__ ull pk2(float a, float b) {
    ull r; asm("mov.b64 %0,{%1,%2};" : "=l"(r) : "f"(a), "f"(b)); return r;
}
__device__ __forceinline__ float hadd2(ull v) {
    float lo, hi; asm("mov.b64 {%0,%1},%2;" : "=f"(lo), "=f"(hi) : "l"(v));
    return lo + hi;
}
__device__ __forceinline__ float tanh_hw(float x) {
    float y; asm("tanh.approx.f32 %0,%1;" : "=f"(y) : "f"(x)); return y;
}

// ---------------------------------------------------------------------------
__global__ void detect_kernel(const int* __restrict__ oh) {
    if (threadIdx.x == 0 && blockIdx.x == 0) {
        int z = 1;
        for (int i = 1; i < 64; i += 2)
            if (oh[i] != 0) { z = 0; break; }
        g_oh64 = z;
    }
}

__global__ void embed_kernel(const float* __restrict__ x,
                             const int* __restrict__ oh,
                             const float* __restrict__ e0,
                             const float* __restrict__ e1,
                             const float* __restrict__ e2,
                             const float* __restrict__ e3,
                             float* __restrict__ origin) {
    int idx = blockIdx.x * blockDim.x + threadIdx.x;
    if (idx >= BB * SS) return;
    int i0, i1, i2, i3;
    if (g_oh64) {
        const int* p = oh + (size_t)idx * 8;
        i0 = p[0]; i1 = p[2]; i2 = p[4]; i3 = p[6];
    } else {
        int4 o = reinterpret_cast<const int4*>(oh)[idx];
        i0 = o.x; i1 = o.y; i2 = o.z; i3 = o.w;
    }
    const float4* xr = reinterpret_cast<const float4*>(x + (size_t)idx * 12);
    float4* out = reinterpret_cast<float4*>(origin + (size_t)idx * FF);
    out[0] = xr[0];
    out[1] = xr[1];
    out[2] = xr[2];
    out[3] = reinterpret_cast<const float4*>(e0)[i0];
    out[4] = reinterpret_cast<const float4*>(e1)[i1];
    const float4* e2p = reinterpret_cast<const float4*>(e2);
    out[5] = e2p[i2 * 2];
    out[6] = e2p[i2 * 2 + 1];
    const float4* e3p = reinterpret_cast<const float4*>(e3);
    out[7] = e3p[i3 * 2];
    out[8] = e3p[i3 * 2 + 1];
}

// ---------------------------------------------------------------------------
// Warp-per-batch GRU. 60 gate rows over 32 lanes, 2 slots/lane:
//   slot0: row = l (0..31)   [all sigmoid: r rows 0..19, z rows 20..31]
//   slot1: row = l+32 (32..59), l<28  [z rows 32..39 on l<8; n rows 40..59 on 8<=l<28]
// K-packed f32x2 dots; x/h live in per-warp smem (float arrays, LDS.128).
// No __syncthreads anywhere — warps fully independent.
// ---------------------------------------------------------------------------
struct WCtx {
    ull wx0[18], wx1[18];   // Wih rows, K-packed
    ull wh0[10], wh1[10];   // Whh rows
    float b0c;              // slot0 combined bias (always sigmoid)
    float b1i, b1h;         // slot1 biases (combined for z-lanes, split for n-lanes)
    bool g2;                // slot1 is an n-row
    int l;
};

__device__ __forceinline__ void load_wctx(
    WCtx& C, int l,
    const float* __restrict__ Wih, const float* __restrict__ Whh,
    const float* __restrict__ bih, const float* __restrict__ bhh) {
    C.l = l;
    int r0 = l;
    int r1 = (l < 28) ? (l + 32) : 59;
    C.g2 = (l >= 8 && l < 28);
#pragma unroll
    for (int i = 0; i < 18; i++) {
        C.wx0[i] = pk2(Wih[r0 * FF + 2 * i], Wih[r0 * FF + 2 * i + 1]);
        C.wx1[i] = pk2(Wih[r1 * FF + 2 * i], Wih[r1 * FF + 2 * i + 1]);
    }
#pragma unroll
    for (int i = 0; i < 10; i++) {
        C.wh0[i] = pk2(Whh[r0 * HH + 2 * i], Whh[r0 * HH + 2 * i + 1]);
        C.wh1[i] = pk2(Whh[r1 * HH + 2 * i], Whh[r1 * HH + 2 * i + 1]);
    }
    C.b0c = bih[r0] + bhh[r0];
    C.b1i = bih[r1];
    C.b1h = bhh[r1];
}

// One GRU cell. xs/hs: per-warp smem float arrays (36 / 20). hprev = this
// lane's h[u] (u = l < 20). Returns raw new h for lanes l<20.
__device__ __forceinline__ float gru_cell_w(
    const WCtx& C, const float* __restrict__ xs, const float* __restrict__ hs,
    float hprev) {
    ull ax0 = 0, ax1 = 0, ah0 = 0, ah1 = 0;
    const ulonglong2* xv = reinterpret_cast<const ulonglong2*>(xs);
#pragma unroll
    for (int i = 0; i < 9; i++) {
        ulonglong2 v = xv[i];
        ax0 = fma2(C.wx0[2 * i], v.x, ax0);
        ax0 = fma2(C.wx0[2 * i + 1], v.y, ax0);
        ax1 = fma2(C.wx1[2 * i], v.x, ax1);
        ax1 = fma2(C.wx1[2 * i + 1], v.y, ax1);
    }
    const ulonglong2* hv = reinterpret_cast<const ulonglong2*>(hs);
#pragma unroll
    for (int i = 0; i < 5; i++) {
        ulonglong2 v = hv[i];
        ah0 = fma2(C.wh0[2 * i], v.x, ah0);
        ah0 = fma2(C.wh0[2 * i + 1], v.y, ah0);
        ah1 = fma2(C.wh1[2 * i], v.x, ah1);
        ah1 = fma2(C.wh1[2 * i + 1], v.y, ah1);
    }
    float sx0 = hadd2(ax0), sh0 = hadd2(ah0);
    float sx1 = hadd2(ax1), sh1 = hadd2(ah1);
    // slot0: always sigmoid (r for l<20, z for 20..31)
    float sig0 = fmaf(0.5f, tanh_hw(0.5f * (sx0 + sh0 + C.b0c)), 0.5f);
    // r needed by n-lanes (slot1 of lanes 8..27, unit u=l-8): r = sig0@(l-8)
    float r = __shfl_sync(FULLMASK, sig0, (C.l - 8) & 31);
    float arg1 = C.g2 ? (sx0 * 0.f + sx1 + C.b1i + r * (sh1 + C.b1h))
                      : (0.5f * (sx1 + sh1 + C.b1i + C.b1h));
    float t1 = tanh_hw(arg1);
    float val1 = C.g2 ? t1 : fmaf(0.5f, t1, 0.5f);
    // gathers for h-update (lanes l<20, u=l):
    float zA = __shfl_sync(FULLMASK, sig0, (20 + C.l) & 31);   // z row 20+u (u<12)
    float zB = __shfl_sync(FULLMASK, val1, (C.l - 12) & 31);   // z row 20+u (u>=12)
    float nn = __shfl_sync(FULLMASK, val1, (C.l + 8) & 31);    // n row 40+u
    float z = (C.l < 12) ? zA : zB;
    return fmaf(z, hprev - nn, nn);
}

// ---------------------------------------------------------------------------
// Encoder: warp per batch, 4-slot x ring with distance-2 float4 prefetch.
// ---------------------------------------------------------------------------
__global__ void __launch_bounds__(64, 4) encoder_kernel(
    const float* __restrict__ xin,
    const float* __restrict__ Wih, const float* __restrict__ Whh,
    const float* __restrict__ bih, const float* __restrict__ bhh) {
    __shared__ __align__(16) float xring[2][4][FF];
    __shared__ __align__(16) float hbuf[2][2][HH];

    int tid = threadIdx.x;
    int w = tid >> 5, l = tid & 31;
    int b = blockIdx.x * 2 + w;

    WCtx C;
    load_wctx(C, l, Wih, Whh, bih, bhh);

    const float* xrow = xin + (size_t)b * SS * FF;
    float* xr_ = &xring[w][0][0];
    float* hb_ = &hbuf[w][0][0];

    // preload x(0), x(1)
    if (l < 9) {
        reinterpret_cast<float4*>(xr_)[l] =
            reinterpret_cast<const float4*>(xrow)[l];
        reinterpret_cast<float4*>(xr_ + FF)[l] =
            reinterpret_cast<const float4*>(xrow + FF)[l];
    }
    if (l < HH) hb_[l] = 0.f;
    __syncwarp();

    float h = 0.f;
    for (int s = 0; s < SS; ++s) {
        float4 pf;
        bool dofetch = (s + 2 < SS) && (l < 9);
        if (dofetch)
            pf = reinterpret_cast<const float4*>(xrow + (size_t)(s + 2) * FF)[l];
        int cur = s & 1;
        float hn = gru_cell_w(C, xr_ + (s & 3) * FF, hb_ + cur * HH, h);
        if (l < HH) { h = hn; hb_[(cur ^ 1) * HH + l] = hn; }
        if (dofetch)
            reinterpret_cast<float4*>(xr_ + ((s + 2) & 3) * FF)[l] = pf;
        __syncwarp();
    }
    if (l < HH) g_h[b * HH + l] = tanh_hw(h);
}

// ---------------------------------------------------------------------------
// Decoder: warp per batch; gates -> tanh -> proj all warp-private.
// proj: slot0 o=l (0..31), slot1 o=l+32 (l<4); Wfc rows K-packed in regs.
// ---------------------------------------------------------------------------
__global__ void __launch_bounds__(64, 4) decoder_kernel(
    const float* __restrict__ Wih, const float* __restrict__ Whh,
    const float* __restrict__ bih, const float* __restrict__ bhh,
    const float* __restrict__ Wfc, const float* __restrict__ bfc,
    float* __restrict__ out_xs) {
    __shared__ __align__(16) float xbuf[2][2][FF];
    __shared__ __align__(16) float hbuf[2][2][HH];

    int tid = threadIdx.x;
    int w = tid >> 5, l = tid & 31;
    int b = blockIdx.x * 2 + w;

    WCtx C;
    load_wctx(C, l, Wih, Whh, bih, bhh);

    int o0 = l;
    int o1 = (l < 4) ? (l + 32) : 35;
    ull wf0[10], wf1[10];
#pragma unroll
    for (int i = 0; i < 10; i++) {
        wf0[i] = pk2(Wfc[o0 * HH + 2 * i], Wfc[o0 * HH + 2 * i + 1]);
        wf1[i] = pk2(Wfc[o1 * HH + 2 * i], Wfc[o1 * HH + 2 * i + 1]);
    }
    float bo0 = bfc[o0], bo1 = bfc[o1];

    float* xb_ = &xbuf[w][0][0];
    float* hb_ = &hbuf[w][0][0];
    float* orow = out_xs + (size_t)b * SS * FF;

    float h = (l < HH) ? g_h[b * HH + l] : 0.f;
    if (l < HH) hb_[l] = h;
    __syncwarp();

    // proj: h(src) -> x(dst smem) + gmem at flipped position so
    auto proj = [&](const float* hsrc, float* xdst, int so) {
        ull a0 = 0, a1 = 0;
        const ulonglong2* hv = reinterpret_cast<const ulonglong2*>(hsrc);
#pragma unroll
        for (int i = 0; i < 5; i++) {
            ulonglong2 v = hv[i];
            a0 = fma2(wf0[2 * i], v.x, a0);
            a0 = fma2(wf0[2 * i + 1], v.y, a0);
            a1 = fma2(wf1[2 * i], v.x, a1);
            a1 = fma2(wf1[2 * i + 1], v.y, a1);
        }
        float x0 = tanh_hw(hadd2(a0) + bo0);
        float x1 = tanh_hw(hadd2(a1) + bo1);
        float* og = orow + (size_t)so * FF;
        og[o0] = x0;
        xdst[o0] = x0;
        if (l < 4) { og[32 + l] = x1; xdst[32 + l] = x1; }
        __syncwarp();
    };

    proj(hb_, xb_, SS - 1);

    for (int st = 1; st < SS; ++st) {
        int cur = (st - 1) & 1, nxt = cur ^ 1;
        float hn = gru_cell_w(C, xb_ + cur * FF, hb_ + cur * HH, h);
        hn = tanh_hw(hn);
        if (l < HH) { h = hn; hb_[nxt * HH + l] = hn; }
        __syncwarp();
        proj(hb_ + nxt * HH, xb_ + nxt * FF, SS - 1 - st);
    }
}

// ---------------------------------------------------------------------------
extern "C" void kernel_launch(void* const* d_in, const int* in_sizes, int n_in,
                              void* d_out, int out_size) {
    const float* x = (const float*)d_in[0];
    const int* oh = (const int*)d_in[1];
    const float* e0 = (const float*)d_in[2];
    const float* e1 = (const float*)d_in[3];
    const float* e2 = (const float*)d_in[4];
    const float* e3 = (const float*)d_in[5];
    const float* Wih1 = (const float*)d_in[6];
    const float* Whh1 = (const float*)d_in[7];
    const float* bih1 = (const float*)d_in[8];
    const float* bhh1 = (const float*)d_in[9];
    const float* Wih2 = (const float*)d_in[10];
    const float* Whh2 = (const float*)d_in[11];
    const float* bih2 = (const float*)d_in[12];
    const float* bhh2 = (const float*)d_in[13];
    const float* Wfc = (const float*)d_in[14];
    const float* bfc = (const float*)d_in[15];

    float* out = (float*)d_out;
    float* origin = out;                          // (B,S,F)
    float* xs = out + (size_t)BB * SS * FF;       // (B,S,F) flipped decode

    detect_kernel<<<1, 32>>>(oh);
    embed_kernel<<<(BB * SS + 255) / 256, 256>>>(x, oh, e0, e1, e2, e3, origin);
    encoder_kernel<<<BB / 2, 64>>>(origin, Wih1, Whh1, bih1, bhh1);
    decoder_kernel<<<BB / 2, 64>>>(Wih2, Whh2, bih2, bhh2, Wfc, bfc, xs);
}